// round 16
// baseline (speedup 1.0000x reference)
#include <cuda_runtime.h>
#include <cuda_fp16.h>
#include <cstdint>

// ---------------- problem constants ----------------
#define BATCH 512
#define NEQv  4096
#define XDIMv 6144
#define H1v   2048
#define H2v   2048
#define YDIMv 4096
#define NEDGE 32768

// ---------------- scratch (device globals; no runtime alloc) ----------------
__device__ __align__(256) __half g_z0[BATCH * XDIMv];   // fp16 activations
__device__ __align__(256) __half g_z1[BATCH * H1v];
__device__ __align__(256) __half g_z2[BATCH * H2v];
// weights fp16, k-pair-interleaved: Wp[(k/2)*N + n] = half2(W[k,n], W[k+1,n])
__device__ __align__(256) __half g_w1[XDIMv * H1v];
__device__ __align__(256) __half g_w2[H1v * H2v];
__device__ __align__(256) __half g_w3[H2v * YDIMv];
__device__ int   g_cnt[NEQv];    // zero at load; self-cleaned by k_build_z
__device__ float g_acc[NEQv];    // zero at load; self-cleaned by k_build_z

// ============================================================
// helpers
// ============================================================
__device__ __forceinline__ unsigned smem_u32(const void* p) {
    return (unsigned)__cvta_generic_to_shared(p);
}
__device__ __forceinline__ void cp16(void* dst, const void* src) {
    asm volatile("cp.async.ca.shared.global [%0], [%1], 16;\n"
                 :: "r"(smem_u32(dst)), "l"(src));
}
#define CP_COMMIT() asm volatile("cp.async.commit_group;\n")
#define CP_WAIT1()  asm volatile("cp.async.wait_group 1;\n")

#define MMA_F16(C, A, B)                                                         \
    asm volatile("mma.sync.aligned.m16n8k16.row.col.f32.f16.f16.f32 "            \
                 "{%0,%1,%2,%3},{%4,%5,%6,%7},{%8,%9},{%0,%1,%2,%3};\n"          \
                 : "+f"((C)[0]), "+f"((C)[1]), "+f"((C)[2]), "+f"((C)[3])         \
                 : "r"((A)[0]), "r"((A)[1]), "r"((A)[2]), "r"((A)[3]),            \
                   "r"((B)[0]), "r"((B)[1]))

#define LDSM_X4(R, ADDR)                                                         \
    asm volatile("ldmatrix.sync.aligned.m8n8.x4.shared.b16 {%0,%1,%2,%3}, [%4];" \
                 : "=r"((R)[0]), "=r"((R)[1]), "=r"((R)[2]), "=r"((R)[3])        \
                 : "r"(ADDR))

// ============================================================
// weight convert into k-pair-interleaved fp16 layout (R11/R12-proven math)
// split into W1 (pre-GEMM1) and W2+W3 (hidden under GEMM1)
// ============================================================
#define N1_8 (XDIMv * H1v / 8)
#define N2_8 (H1v * H2v / 8)
#define N3_8 (H2v * YDIMv / 8)

__device__ __forceinline__ void wconv_one(const float* __restrict__ W,
                                          __half* __restrict__ Wp,
                                          int j, int n4shift) {
    const int n4mask = (1 << n4shift) - 1;
    int kp = j >> n4shift;
    int nb = j & n4mask;
    const float4* Wv = (const float4*)W;
    float4 r0 = Wv[((size_t)(2 * kp) << n4shift) + nb];
    float4 r1 = Wv[((size_t)(2 * kp + 1) << n4shift) + nb];
    __half2 h0 = __floats2half2_rn(r0.x, r1.x);
    __half2 h1 = __floats2half2_rn(r0.y, r1.y);
    __half2 h2 = __floats2half2_rn(r0.z, r1.z);
    __half2 h3 = __floats2half2_rn(r0.w, r1.w);
    uint4 h;
    h.x = *(uint32_t*)&h0; h.y = *(uint32_t*)&h1;
    h.z = *(uint32_t*)&h2; h.w = *(uint32_t*)&h3;
    ((uint4*)Wp)[j] = h;
}

__global__ void k_wconv1(const float* __restrict__ W1) {
    int i = blockIdx.x * blockDim.x + threadIdx.x;
    wconv_one(W1, g_w1, i, 9);                    // N=2048
}
__global__ void k_wconv23(const float* __restrict__ W2, const float* __restrict__ W3) {
    int i = blockIdx.x * blockDim.x + threadIdx.x;
    if (i < N2_8) {
        wconv_one(W2, g_w2, i, 9);                // N=2048
    } else {
        wconv_one(W3, g_w3, i - N2_8, 10);        // N=4096
    }
}

// ============================================================
// GCN kernels (proven)
// ============================================================
__global__ void k_count(const int* __restrict__ ei) {
    int e = blockIdx.x * blockDim.x + threadIdx.x;
    if (e < NEDGE) atomicAdd(&g_cnt[ei[NEDGE + e]], 1);
}
__global__ void k_scatter(const int* __restrict__ ei, const float* __restrict__ x,
                          const float* __restrict__ gw) {
    int e = blockIdx.x * blockDim.x + threadIdx.x;
    if (e >= NEDGE) return;
    int s = ei[e];
    int d = ei[NEDGE + e];
    float deg_s = 1.f + 512.f * (float)g_cnt[s];
    float xw = gw[0] * x[(size_t)(s & 511) * XDIMv + (s >> 9)];
    atomicAdd(&g_acc[d], rsqrtf(deg_s) * xw);
}
// float2 + self-clean (proven bit-identical across replays in R13-R15)
__global__ void k_build_z(const float* __restrict__ x, const float* __restrict__ gw,
                          const float* __restrict__ gb) {
    int j = (blockIdx.x * blockDim.x + threadIdx.x) * 2;
    int b = blockIdx.y;
    float2 v = *(const float2*)&x[(size_t)b * XDIMv + j];
    float z0, z1;
    if (j >= NEQv) {
        z0 = v.x; z1 = v.y;
    } else {
        float w = gw[0], bb = gb[0];
        float xw0 = w * v.x, xw1 = w * v.y;
        float o0, o1;
        if (j < 8) {
            int i0 = (j << 9) + b;
            int i1 = ((j + 1) << 9) + b;
            float deg0 = 1.f + 512.f * (float)g_cnt[i0];
            float deg1 = 1.f + 512.f * (float)g_cnt[i1];
            o0 = xw0 / deg0 + 512.f * rsqrtf(deg0) * g_acc[i0] + bb;
            o1 = xw1 / deg1 + 512.f * rsqrtf(deg1) * g_acc[i1] + bb;
            g_acc[i0] = 0.f; g_cnt[i0] = 0;   // self-clean for next replay
            g_acc[i1] = 0.f; g_cnt[i1] = 0;
        } else {
            o0 = xw0 + bb;
            o1 = xw1 + bb;
        }
        z0 = fmaxf(o0, 0.f);
        z1 = fmaxf(o1, 0.f);
    }
    __half2 p = __floats2half2_rn(z0, z1);
    *(__half2*)&g_z0[(size_t)b * XDIMv + j] = p;
}

// ============================================================
// GEMM (R12-proven verbatim): C[M,N] = act(A[M,K] @ W[K,N] + bias)
// ============================================================
#define BM 128
#define BN 64
#define BK 64
#define APITCH 72                      // halfs per A smem row (144 B)
#define BPITCH32 72                    // uint32 per B smem row (288 B)
#define A_BYTES (BM * APITCH * 2)      // 18432
#define B_BYTES (32 * BPITCH32 * 4)    // 9216
#define STAGE_BYTES (A_BYTES + B_BYTES)        // 27648
#define STAGES 3
#define GEMM_SMEM_BYTES (STAGES * STAGE_BYTES) // 82944

template<int RELU>
__global__ void __launch_bounds__(256, 2) k_gemm(
    const __half* __restrict__ A, const __half* __restrict__ W,
    const float* __restrict__ bias, void* __restrict__ outp,
    int M, int N, int K)
{
    extern __shared__ char smem[];
    const int tid  = threadIdx.x;
    const int lane = tid & 31;
    const int wid  = tid >> 5;
    const int wm   = wid & 3;
    const int wn   = wid >> 2;
    const int m0   = blockIdx.y * BM;
    const int n0   = blockIdx.x * BN;
    const int r    = lane >> 2;
    const int q    = lane & 3;

    const int lrow = lane & 15;
    const int lkof = (lane >> 4) << 3;

    float c[2][4][4];
#pragma unroll
    for (int i = 0; i < 2; i++)
#pragma unroll
        for (int j = 0; j < 4; j++)
#pragma unroll
            for (int k = 0; k < 4; k++) c[i][j][k] = 0.f;

    const int kIters = K / BK;
    const uint32_t* Wp = (const uint32_t*)W;

    auto loadStage = [&](int it, int stg) {
        const int k0 = it * BK;
        char* st = smem + stg * STAGE_BYTES;
#pragma unroll
        for (int t = 0; t < 4; t++) {
            int id = tid + t * 256;
            int rr = id >> 3, ch = id & 7;
            const __half* src = A + (size_t)(m0 + rr) * K + k0 + ch * 8;
            cp16(st + rr * (APITCH * 2) + ch * 16, src);
        }
#pragma unroll
        for (int t = 0; t < 2; t++) {
            int id = tid + t * 256;
            int rr = id >> 4, ch = id & 15;
            const uint32_t* src = Wp + (size_t)(k0 / 2 + rr) * N + n0 + ch * 4;
            cp16(st + A_BYTES + rr * (BPITCH32 * 4) + ch * 16, src);
        }
    };

    loadStage(0, 0); CP_COMMIT();
    loadStage(1, 1); CP_COMMIT();

    int stg = 0;
    for (int it = 0; it < kIters; ++it) {
        CP_WAIT1();
        __syncthreads();
        if (it + 2 < kIters) loadStage(it + 2, (stg + 2) % STAGES);
        CP_COMMIT();

        const char* st = smem + stg * STAGE_BYTES;
        const uint32_t sAu = smem_u32(st);
        const uint32_t* sB = (const uint32_t*)(st + A_BYTES);

#pragma unroll
        for (int kk = 0; kk < BK; kk += 16) {
            uint32_t ah[2][4], bh[4][2];
#pragma unroll
            for (int mt = 0; mt < 2; mt++) {
                const uint32_t addr = sAu
                    + (uint32_t)(wm * 32 + mt * 16 + lrow) * (APITCH * 2)
                    + (uint32_t)(kk + lkof) * 2;
                LDSM_X4(ah[mt], addr);
            }
            const int p0 = (kk >> 1) + q;
#pragma unroll
            for (int nt = 0; nt < 4; nt++) {
                const int n  = wn * 32 + nt * 8 + r;
                const int i0 = p0 * BPITCH32 + n;
                bh[nt][0] = sB[i0];
                bh[nt][1] = sB[i0 + 4 * BPITCH32];
            }
#pragma unroll
            for (int mt = 0; mt < 2; mt++)
#pragma unroll
                for (int nt = 0; nt < 4; nt++)
                    MMA_F16(c[mt][nt], ah[mt], bh[nt]);
        }
        stg = (stg + 1) % STAGES;
    }

    // ---------------- epilogue ----------------
#pragma unroll
    for (int mt = 0; mt < 2; mt++) {
#pragma unroll
        for (int nt = 0; nt < 4; nt++) {
            int row0 = m0 + wm * 32 + mt * 16 + r;
            int col0 = n0 + wn * 32 + nt * 8 + 2 * q;
            float bb0 = bias[col0], bb1 = bias[col0 + 1];
            float v00 = c[mt][nt][0] + bb0, v01 = c[mt][nt][1] + bb1;
            float v10 = c[mt][nt][2] + bb0, v11 = c[mt][nt][3] + bb1;
            if (RELU) {
                __half2 p0 = __floats2half2_rn(fmaxf(v00, 0.f), fmaxf(v01, 0.f));
                __half2 p1 = __floats2half2_rn(fmaxf(v10, 0.f), fmaxf(v11, 0.f));
                __half* z = (__half*)outp;
                *(__half2*)&z[(size_t)row0 * N + col0]       = p0;
                *(__half2*)&z[(size_t)(row0 + 8) * N + col0] = p1;
            } else {
                float* o = (float*)outp;
                *(float2*)&o[(size_t)row0 * N + col0]       = make_float2(v00, v01);
                *(float2*)&o[(size_t)(row0 + 8) * N + col0] = make_float2(v10, v11);
            }
        }
    }
}

// ============================================================
// launch: wconv1 overlaps the GCN chain; wconv23 hides under GEMM1.
// ============================================================
extern "C" void kernel_launch(void* const* d_in, const int* in_sizes, int n_in,
                              void* d_out, int out_size) {
    const float* x  = (const float*)d_in[0];
    const int*   ei = (const int*)  d_in[1];
    const float* gw = (const float*)d_in[2];
    const float* gb = (const float*)d_in[3];
    const float* W1 = (const float*)d_in[4];
    const float* b1 = (const float*)d_in[5];
    const float* W2 = (const float*)d_in[6];
    const float* b2 = (const float*)d_in[7];
    const float* W3 = (const float*)d_in[8];
    const float* b3 = (const float*)d_in[9];
    float* out = (float*)d_out;

    static cudaStream_t s1 = nullptr;
    static cudaEvent_t evFork = nullptr, evW1 = nullptr, evW23 = nullptr;
    if (!s1) {
        cudaStreamCreateWithFlags(&s1, cudaStreamNonBlocking);
        cudaEventCreateWithFlags(&evFork, cudaEventDisableTiming);
        cudaEventCreateWithFlags(&evW1,  cudaEventDisableTiming);
        cudaEventCreateWithFlags(&evW23, cudaEventDisableTiming);
        cudaFuncSetAttribute(k_gemm<1>, cudaFuncAttributeMaxDynamicSharedMemorySize, GEMM_SMEM_BYTES);
        cudaFuncSetAttribute(k_gemm<0>, cudaFuncAttributeMaxDynamicSharedMemorySize, GEMM_SMEM_BYTES);
    }

    void *z0p, *z1p, *z2p, *w1p, *w2p, *w3p;
    cudaGetSymbolAddress(&z0p, g_z0);
    cudaGetSymbolAddress(&z1p, g_z1);
    cudaGetSymbolAddress(&z2p, g_z2);
    cudaGetSymbolAddress(&w1p, g_w1);
    cudaGetSymbolAddress(&w2p, g_w2);
    cudaGetSymbolAddress(&w3p, g_w3);

    // fork side stream
    cudaEventRecord(evFork, 0);
    cudaStreamWaitEvent(s1, evFork, 0);
    // W1 conversion — overlaps the GCN chain below
    k_wconv1<<<N1_8 / 256, 256, 0, s1>>>(W1);
    cudaEventRecord(evW1, s1);
    // W2+W3 conversion — hides under GEMM1
    k_wconv23<<<(N2_8 + N3_8) / 256, 256, 0, s1>>>(W2, W3);
    cudaEventRecord(evW23, s1);

    // GCN chain on main stream
    k_count<<<NEDGE / 256, 256>>>(ei);
    k_scatter<<<NEDGE / 256, 256>>>(ei, x, gw);
    k_build_z<<<dim3(XDIMv / 2 / 256, BATCH), 256>>>(x, gw, gb);

    // GEMM1 needs z0 (main) + w1 (side)
    cudaStreamWaitEvent(0, evW1, 0);
    dim3 g1(H1v / BN,   BATCH / BM);
    k_gemm<1><<<g1, 256, GEMM_SMEM_BYTES>>>(
        (const __half*)z0p, (const __half*)w1p, b1, z1p, BATCH, H1v, XDIMv);

    // GEMM2 additionally needs w2/w3 conversion done
    cudaStreamWaitEvent(0, evW23, 0);
    dim3 g2(H2v / BN,   BATCH / BM);
    dim3 g3(YDIMv / BN, BATCH / BM);
    k_gemm<1><<<g2, 256, GEMM_SMEM_BYTES>>>(
        (const __half*)z1p, (const __half*)w2p, b2, z2p, BATCH, H2v, H1v);
    k_gemm<0><<<g3, 256, GEMM_SMEM_BYTES>>>(
        (const __half*)z2p, (const __half*)w3p, b3, out, BATCH, YDIMv, H2v);
}

// round 17
// speedup vs baseline: 1.0182x; 1.0182x over previous
#include <cuda_runtime.h>
#include <cuda_fp16.h>
#include <cstdint>

// ---------------- problem constants ----------------
#define BATCH 512
#define NEQv  4096
#define XDIMv 6144
#define H1v   2048
#define H2v   2048
#define YDIMv 4096
#define NEDGE 32768

// ---------------- scratch (device globals; no runtime alloc) ----------------
__device__ __align__(256) __half g_z0[BATCH * XDIMv];   // fp16 activations
__device__ __align__(256) __half g_z1[BATCH * H1v];
__device__ __align__(256) __half g_z2[BATCH * H2v];
// weights fp16, k-pair-interleaved: Wp[(k/2)*N + n] = half2(W[k,n], W[k+1,n])
__device__ __align__(256) __half g_w1[XDIMv * H1v];
__device__ __align__(256) __half g_w2[H1v * H2v];
__device__ __align__(256) __half g_w3[H2v * YDIMv];
__device__ int   g_cnt[NEQv];    // zero at load; self-cleaned by k_build_z
__device__ float g_acc[NEQv];    // zero at load; self-cleaned by k_build_z

// ============================================================
// helpers
// ============================================================
__device__ __forceinline__ unsigned smem_u32(const void* p) {
    return (unsigned)__cvta_generic_to_shared(p);
}
__device__ __forceinline__ void cp16(void* dst, const void* src) {
    asm volatile("cp.async.ca.shared.global [%0], [%1], 16;\n"
                 :: "r"(smem_u32(dst)), "l"(src));
}
#define CP_COMMIT() asm volatile("cp.async.commit_group;\n")
#define CP_WAIT1()  asm volatile("cp.async.wait_group 1;\n")

#define MMA_F16(C, A, B)                                                         \
    asm volatile("mma.sync.aligned.m16n8k16.row.col.f32.f16.f16.f32 "            \
                 "{%0,%1,%2,%3},{%4,%5,%6,%7},{%8,%9},{%0,%1,%2,%3};\n"          \
                 : "+f"((C)[0]), "+f"((C)[1]), "+f"((C)[2]), "+f"((C)[3])         \
                 : "r"((A)[0]), "r"((A)[1]), "r"((A)[2]), "r"((A)[3]),            \
                   "r"((B)[0]), "r"((B)[1]))

#define LDSM_X4(R, ADDR)                                                         \
    asm volatile("ldmatrix.sync.aligned.m8n8.x4.shared.b16 {%0,%1,%2,%3}, [%4];" \
                 : "=r"((R)[0]), "=r"((R)[1]), "=r"((R)[2]), "=r"((R)[3])        \
                 : "r"(ADDR))

// ============================================================
// weight convert into k-pair-interleaved fp16 layout (R11/R12-proven math)
// ============================================================
#define N1_8 (XDIMv * H1v / 8)          // 1572864
#define N2_8 (H1v * H2v / 8)            //  524288
#define N3_8 (H2v * YDIMv / 8)          // 1048576
#define W1BLKS (N1_8 / 256)             // 6144
#define W23BLKS ((N2_8 + N3_8) / 256)   // 6144
#define GCNBLKS (NEDGE / 256)           // 128

__device__ __forceinline__ void wconv_one(const float* __restrict__ W,
                                          __half* __restrict__ Wp,
                                          int j, int n4shift) {
    const int n4mask = (1 << n4shift) - 1;
    int kp = j >> n4shift;
    int nb = j & n4mask;
    const float4* Wv = (const float4*)W;
    float4 r0 = Wv[((size_t)(2 * kp) << n4shift) + nb];
    float4 r1 = Wv[((size_t)(2 * kp + 1) << n4shift) + nb];
    __half2 h0 = __floats2half2_rn(r0.x, r1.x);
    __half2 h1 = __floats2half2_rn(r0.y, r1.y);
    __half2 h2 = __floats2half2_rn(r0.z, r1.z);
    __half2 h3 = __floats2half2_rn(r0.w, r1.w);
    uint4 h;
    h.x = *(uint32_t*)&h0; h.y = *(uint32_t*)&h1;
    h.z = *(uint32_t*)&h2; h.w = *(uint32_t*)&h3;
    ((uint4*)Wp)[j] = h;
}

// ============================================================
// fused kernel 1: W1 conversion (blocks [0, W1BLKS)) + edge count (tail)
// ============================================================
__global__ void k_count_w1(const int* __restrict__ ei, const float* __restrict__ W1) {
    int blk = blockIdx.x;
    if (blk < W1BLKS) {
        wconv_one(W1, g_w1, blk * 256 + threadIdx.x, 9);     // N=2048
    } else {
        int e = (blk - W1BLKS) * 256 + threadIdx.x;
        if (e < NEDGE) atomicAdd(&g_cnt[ei[NEDGE + e]], 1);
    }
}

// ============================================================
// fused kernel 2: W2+W3 conversion + edge scatter (tail blocks)
// ============================================================
__global__ void k_scatter_w23(const int* __restrict__ ei, const float* __restrict__ x,
                              const float* __restrict__ gw,
                              const float* __restrict__ W2, const float* __restrict__ W3) {
    int blk = blockIdx.x;
    if (blk < W23BLKS) {
        int i = blk * 256 + threadIdx.x;
        if (i < N2_8) wconv_one(W2, g_w2, i, 9);             // N=2048
        else          wconv_one(W3, g_w3, i - N2_8, 10);     // N=4096
    } else {
        int e = (blk - W23BLKS) * 256 + threadIdx.x;
        if (e < NEDGE) {
            int s = ei[e];
            int d = ei[NEDGE + e];
            float deg_s = 1.f + 512.f * (float)g_cnt[s];
            float xw = gw[0] * x[(size_t)(s & 511) * XDIMv + (s >> 9)];
            atomicAdd(&g_acc[d], rsqrtf(deg_s) * xw);
        }
    }
}

// ============================================================
// build_z: R12 float2 shape + self-clean (proven bit-identical)
// ============================================================
__global__ void k_build_z(const float* __restrict__ x, const float* __restrict__ gw,
                          const float* __restrict__ gb) {
    int j = (blockIdx.x * blockDim.x + threadIdx.x) * 2;
    int b = blockIdx.y;
    float2 v = *(const float2*)&x[(size_t)b * XDIMv + j];
    float z0, z1;
    if (j >= NEQv) {
        z0 = v.x; z1 = v.y;
    } else {
        float w = gw[0], bb = gb[0];
        float xw0 = w * v.x, xw1 = w * v.y;
        float o0, o1;
        if (j < 8) {
            int i0 = (j << 9) + b;
            int i1 = ((j + 1) << 9) + b;
            float deg0 = 1.f + 512.f * (float)g_cnt[i0];
            float deg1 = 1.f + 512.f * (float)g_cnt[i1];
            o0 = xw0 / deg0 + 512.f * rsqrtf(deg0) * g_acc[i0] + bb;
            o1 = xw1 / deg1 + 512.f * rsqrtf(deg1) * g_acc[i1] + bb;
            g_acc[i0] = 0.f; g_cnt[i0] = 0;   // self-clean for next replay
            g_acc[i1] = 0.f; g_cnt[i1] = 0;
        } else {
            o0 = xw0 + bb;
            o1 = xw1 + bb;
        }
        z0 = fmaxf(o0, 0.f);
        z1 = fmaxf(o1, 0.f);
    }
    __half2 p = __floats2half2_rn(z0, z1);
    *(__half2*)&g_z0[(size_t)b * XDIMv + j] = p;
}

// ============================================================
// GEMM (R12-proven verbatim): C[M,N] = act(A[M,K] @ W[K,N] + bias)
// A: fp16 [M,K] -> padded smem rows -> ldmatrix.x4 (conflict-free)
// B: fp16 k-pair-interleaved [(K/2) x N] half2 -> LDS.32 fragments
// Pure fp16 MMA (fp32 accumulate). CTA 128x64, BK=64, 3-stage, occ 2.
// ============================================================
#define BM 128
#define BN 64
#define BK 64
#define APITCH 72                      // halfs per A smem row (144 B)
#define BPITCH32 72                    // uint32 per B smem row (288 B)
#define A_BYTES (BM * APITCH * 2)      // 18432
#define B_BYTES (32 * BPITCH32 * 4)    // 9216
#define STAGE_BYTES (A_BYTES + B_BYTES)        // 27648
#define STAGES 3
#define GEMM_SMEM_BYTES (STAGES * STAGE_BYTES) // 82944

template<int RELU>
__global__ void __launch_bounds__(256, 2) k_gemm(
    const __half* __restrict__ A, const __half* __restrict__ W,
    const float* __restrict__ bias, void* __restrict__ outp,
    int M, int N, int K)
{
    extern __shared__ char smem[];
    const int tid  = threadIdx.x;
    const int lane = tid & 31;
    const int wid  = tid >> 5;
    const int wm   = wid & 3;
    const int wn   = wid >> 2;
    const int m0   = blockIdx.y * BM;
    const int n0   = blockIdx.x * BN;
    const int r    = lane >> 2;
    const int q    = lane & 3;

    const int lrow = lane & 15;
    const int lkof = (lane >> 4) << 3;

    float c[2][4][4];
#pragma unroll
    for (int i = 0; i < 2; i++)
#pragma unroll
        for (int j = 0; j < 4; j++)
#pragma unroll
            for (int k = 0; k < 4; k++) c[i][j][k] = 0.f;

    const int kIters = K / BK;
    const uint32_t* Wp = (const uint32_t*)W;

    auto loadStage = [&](int it, int stg) {
        const int k0 = it * BK;
        char* st = smem + stg * STAGE_BYTES;
#pragma unroll
        for (int t = 0; t < 4; t++) {
            int id = tid + t * 256;
            int rr = id >> 3, ch = id & 7;
            const __half* src = A + (size_t)(m0 + rr) * K + k0 + ch * 8;
            cp16(st + rr * (APITCH * 2) + ch * 16, src);
        }
#pragma unroll
        for (int t = 0; t < 2; t++) {
            int id = tid + t * 256;
            int rr = id >> 4, ch = id & 15;
            const uint32_t* src = Wp + (size_t)(k0 / 2 + rr) * N + n0 + ch * 4;
            cp16(st + A_BYTES + rr * (BPITCH32 * 4) + ch * 16, src);
        }
    };

    loadStage(0, 0); CP_COMMIT();
    loadStage(1, 1); CP_COMMIT();

    int stg = 0;
    for (int it = 0; it < kIters; ++it) {
        CP_WAIT1();
        __syncthreads();
        if (it + 2 < kIters) loadStage(it + 2, (stg + 2) % STAGES);
        CP_COMMIT();

        const char* st = smem + stg * STAGE_BYTES;
        const uint32_t sAu = smem_u32(st);
        const uint32_t* sB = (const uint32_t*)(st + A_BYTES);

#pragma unroll
        for (int kk = 0; kk < BK; kk += 16) {
            uint32_t ah[2][4], bh[4][2];
#pragma unroll
            for (int mt = 0; mt < 2; mt++) {
                const uint32_t addr = sAu
                    + (uint32_t)(wm * 32 + mt * 16 + lrow) * (APITCH * 2)
                    + (uint32_t)(kk + lkof) * 2;
                LDSM_X4(ah[mt], addr);
            }
            const int p0 = (kk >> 1) + q;
#pragma unroll
            for (int nt = 0; nt < 4; nt++) {
                const int n  = wn * 32 + nt * 8 + r;
                const int i0 = p0 * BPITCH32 + n;
                bh[nt][0] = sB[i0];
                bh[nt][1] = sB[i0 + 4 * BPITCH32];
            }
#pragma unroll
            for (int mt = 0; mt < 2; mt++)
#pragma unroll
                for (int nt = 0; nt < 4; nt++)
                    MMA_F16(c[mt][nt], ah[mt], bh[nt]);
        }
        stg = (stg + 1) % STAGES;
    }

    // ---------------- epilogue ----------------
#pragma unroll
    for (int mt = 0; mt < 2; mt++) {
#pragma unroll
        for (int nt = 0; nt < 4; nt++) {
            int row0 = m0 + wm * 32 + mt * 16 + r;
            int col0 = n0 + wn * 32 + nt * 8 + 2 * q;
            float bb0 = bias[col0], bb1 = bias[col0 + 1];
            float v00 = c[mt][nt][0] + bb0, v01 = c[mt][nt][1] + bb1;
            float v10 = c[mt][nt][2] + bb0, v11 = c[mt][nt][3] + bb1;
            if (RELU) {
                __half2 p0 = __floats2half2_rn(fmaxf(v00, 0.f), fmaxf(v01, 0.f));
                __half2 p1 = __floats2half2_rn(fmaxf(v10, 0.f), fmaxf(v11, 0.f));
                __half* z = (__half*)outp;
                *(__half2*)&z[(size_t)row0 * N + col0]       = p0;
                *(__half2*)&z[(size_t)(row0 + 8) * N + col0] = p1;
            } else {
                float* o = (float*)outp;
                *(float2*)&o[(size_t)row0 * N + col0]       = make_float2(v00, v01);
                *(float2*)&o[(size_t)(row0 + 8) * N + col0] = make_float2(v10, v11);
            }
        }
    }
}

// ============================================================
// launch: single stream, wconv folded into the GCN kernels as extra blocks
// ============================================================
extern "C" void kernel_launch(void* const* d_in, const int* in_sizes, int n_in,
                              void* d_out, int out_size) {
    const float* x  = (const float*)d_in[0];
    const int*   ei = (const int*)  d_in[1];
    const float* gw = (const float*)d_in[2];
    const float* gb = (const float*)d_in[3];
    const float* W1 = (const float*)d_in[4];
    const float* b1 = (const float*)d_in[5];
    const float* W2 = (const float*)d_in[6];
    const float* b2 = (const float*)d_in[7];
    const float* W3 = (const float*)d_in[8];
    const float* b3 = (const float*)d_in[9];
    float* out = (float*)d_out;

    cudaFuncSetAttribute(k_gemm<1>, cudaFuncAttributeMaxDynamicSharedMemorySize, GEMM_SMEM_BYTES);
    cudaFuncSetAttribute(k_gemm<0>, cudaFuncAttributeMaxDynamicSharedMemorySize, GEMM_SMEM_BYTES);

    void *z0p, *z1p, *z2p, *w1p, *w2p, *w3p;
    cudaGetSymbolAddress(&z0p, g_z0);
    cudaGetSymbolAddress(&z1p, g_z1);
    cudaGetSymbolAddress(&z2p, g_z2);
    cudaGetSymbolAddress(&w1p, g_w1);
    cudaGetSymbolAddress(&w2p, g_w2);
    cudaGetSymbolAddress(&w3p, g_w3);

    // fused GCN + weight conversion chain (single stream)
    k_count_w1<<<W1BLKS + GCNBLKS, 256>>>(ei, W1);
    k_scatter_w23<<<W23BLKS + GCNBLKS, 256>>>(ei, x, gw, W2, W3);
    k_build_z<<<dim3(XDIMv / 2 / 256, BATCH), 256>>>(x, gw, gb);

    // MLP
    dim3 g1(H1v / BN,   BATCH / BM);
    dim3 g2(H2v / BN,   BATCH / BM);
    dim3 g3(YDIMv / BN, BATCH / BM);
    k_gemm<1><<<g1, 256, GEMM_SMEM_BYTES>>>(
        (const __half*)z0p, (const __half*)w1p, b1, z1p, BATCH, H1v, XDIMv);
    k_gemm<1><<<g2, 256, GEMM_SMEM_BYTES>>>(
        (const __half*)z1p, (const __half*)w2p, b2, z2p, BATCH, H2v, H1v);
    k_gemm<0><<<g3, 256, GEMM_SMEM_BYTES>>>(
        (const __half*)z2p, (const __half*)w3p, b3, out, BATCH, YDIMv, H2v);
}